// round 5
// baseline (speedup 1.0000x reference)
#include <cuda_runtime.h>
#include <cuda_bf16.h>
#include <math.h>

#define D        512
#define DV       128          // D/4 float4 per row
#define MAXN     8192
#define KTOP     12
#define NROUNDS  14
#define THRESH_F 0.5f
#define LDS      40           // padded smem stride (bf16 elems) for ldmatrix, conflict-free
#define GREEDY_SMEM (MAXN * KTOP * 2 + 2 * MAXN)   // 212992 bytes

// ---------------- device state (static scratch; no allocations) ----------------
__device__ float                        g_emb[2][(size_t)MAXN * D];   // fp32 master (ping-pong)
__device__ __align__(16) __nv_bfloat16  g_embh[2][(size_t)MAXN * D];  // bf16 mirror for MMA
__device__ float                        g_invnorm[MAXN];
__device__ float                        g_G[(size_t)MAXN * MAXN];     // raw dots, stride MAXN
__device__ unsigned short               g_topk[MAXN * KTOP];
__device__ unsigned char                g_trunc[MAXN];
__device__ int                          g_partner[MAXN];
__device__ int                          g_surv[MAXN];
__device__ int                          g_n, g_newn, g_nmerge, g_done, g_src;

// ---------------- PTX helpers ----------------
__device__ __forceinline__ void ldm_x4(unsigned& r0, unsigned& r1, unsigned& r2, unsigned& r3,
                                       unsigned addr) {
    asm volatile("ldmatrix.sync.aligned.m8n8.x4.shared.b16 {%0,%1,%2,%3}, [%4];\n"
                 : "=r"(r0), "=r"(r1), "=r"(r2), "=r"(r3) : "r"(addr));
}
__device__ __forceinline__ void ldm_x4_t(unsigned& r0, unsigned& r1, unsigned& r2, unsigned& r3,
                                         unsigned addr) {
    asm volatile("ldmatrix.sync.aligned.m8n8.x4.trans.shared.b16 {%0,%1,%2,%3}, [%4];\n"
                 : "=r"(r0), "=r"(r1), "=r"(r2), "=r"(r3) : "r"(addr));
}
__device__ __forceinline__ void mma16816(float* c, const unsigned* a, unsigned b0, unsigned b1) {
    asm volatile(
        "mma.sync.aligned.m16n8k16.row.col.f32.bf16.bf16.f32 "
        "{%0,%1,%2,%3}, {%4,%5,%6,%7}, {%8,%9}, {%0,%1,%2,%3};\n"
        : "+f"(c[0]), "+f"(c[1]), "+f"(c[2]), "+f"(c[3])
        : "r"(a[0]), "r"(a[1]), "r"(a[2]), "r"(a[3]), "r"(b0), "r"(b1));
}

// ---------------- init: copy input (fp32 + bf16), inverse norms, reset control ----------------
__global__ void __launch_bounds__(128) k_init(const float* __restrict__ in, int n0) {
    int i = blockIdx.x;
    int t = threadIdx.x;
    __shared__ float sred[128];
    float4 v = ((const float4*)in)[(size_t)i * DV + t];
    ((float4*)g_emb[0])[(size_t)i * DV + t] = v;
    __nv_bfloat162* H = (__nv_bfloat162*)g_embh[0];
    H[(size_t)i * 256 + t * 2]     = __floats2bfloat162_rn(v.x, v.y);
    H[(size_t)i * 256 + t * 2 + 1] = __floats2bfloat162_rn(v.z, v.w);
    sred[t] = v.x * v.x + v.y * v.y + v.z * v.z + v.w * v.w;
    __syncthreads();
    for (int off = 64; off > 0; off >>= 1) {
        if (t < off) sred[t] += sred[t + off];
        __syncthreads();
    }
    if (t == 0) g_invnorm[i] = 1.0f / fmaxf(sqrtf(sred[0]), 1e-8f);
    if (i == 0 && t == 0) {
        g_n = n0; g_done = 0; g_src = 0; g_newn = n0; g_nmerge = 0;
    }
}

// ---------------- gram via bf16 tensor cores: G = E E^T (skip tiles below diagonal) ----------------
__global__ void __launch_bounds__(256) k_gemm() {
    if (g_done) return;
    int n = g_n;
    if (n <= 1) return;
    int row0 = blockIdx.y << 7, col0 = blockIdx.x << 7;
    if (row0 >= n || col0 >= n) return;
    if (col0 + 127 <= row0) return;                 // tile entirely j<=i: skip
    const __nv_bfloat16* __restrict__ E = g_embh[g_src];

    __shared__ __nv_bfloat16 As[128 * LDS];
    __shared__ __nv_bfloat16 Bs[128 * LDS];
    int tid = threadIdx.x, lane = tid & 31, wid = tid >> 5;
    int wm = wid >> 2, wn = wid & 3;                // warp tile: rows wm*64, cols wn*32

    float c[4][4][4];
#pragma unroll
    for (int mi = 0; mi < 4; mi++)
#pragma unroll
        for (int ni = 0; ni < 4; ni++)
#pragma unroll
            for (int q = 0; q < 4; q++) c[mi][ni][q] = 0.0f;

    unsigned sA = (unsigned)__cvta_generic_to_shared(As);
    unsigned sB = (unsigned)__cvta_generic_to_shared(Bs);
    int lrow = lane & 15, lcol = (lane >> 4) << 3;  // ldmatrix lane addressing

    int r_ld = tid >> 2, c_ld = (tid & 3) << 3;     // gmem->smem: 16B per thread per half
    const __nv_bfloat16* pa = E + (size_t)(row0 + r_ld) * D + c_ld;
    const __nv_bfloat16* pb = E + (size_t)(col0 + r_ld) * D + c_ld;

    for (int k0 = 0; k0 < D; k0 += 32) {
        __syncthreads();
#pragma unroll
        for (int half = 0; half < 2; half++) {      // rows r_ld and r_ld+64
            *(uint4*)&As[(r_ld + half * 64) * LDS + c_ld] =
                *(const uint4*)(pa + (size_t)half * 64 * D + k0);
            *(uint4*)&Bs[(r_ld + half * 64) * LDS + c_ld] =
                *(const uint4*)(pb + (size_t)half * 64 * D + k0);
        }
        __syncthreads();
#pragma unroll
        for (int ks = 0; ks < 32; ks += 16) {
            unsigned a[4][4], bt[2][4];
#pragma unroll
            for (int mi = 0; mi < 4; mi++)
                ldm_x4(a[mi][0], a[mi][1], a[mi][2], a[mi][3],
                       sA + (unsigned)(((wm * 64 + mi * 16 + lrow) * LDS + ks + lcol) * 2));
#pragma unroll
            for (int np = 0; np < 2; np++)
                ldm_x4_t(bt[np][0], bt[np][1], bt[np][2], bt[np][3],
                         sB + (unsigned)(((wn * 32 + np * 16 + lrow) * LDS + ks + lcol) * 2));
            // b-frags: ni=0:(bt0[0],bt0[2]) ni=1:(bt0[1],bt0[3]) ni=2:(bt1[0],bt1[2]) ni=3:(bt1[1],bt1[3])
#pragma unroll
            for (int mi = 0; mi < 4; mi++) {
                mma16816(c[mi][0], a[mi], bt[0][0], bt[0][2]);
                mma16816(c[mi][1], a[mi], bt[0][1], bt[0][3]);
                mma16816(c[mi][2], a[mi], bt[1][0], bt[1][2]);
                mma16816(c[mi][3], a[mi], bt[1][1], bt[1][3]);
            }
        }
    }

    int gr = lane >> 2, gc = (lane & 3) << 1;
#pragma unroll
    for (int mi = 0; mi < 4; mi++) {
#pragma unroll
        for (int ni = 0; ni < 4; ni++) {
            int i0 = row0 + wm * 64 + mi * 16 + gr;
            int j0 = col0 + wn * 32 + ni * 8 + gc;
#pragma unroll
            for (int h = 0; h < 2; h++) {           // rows gr and gr+8
                int i = i0 + h * 8;
                if (i < n) {
                    size_t base = (size_t)i * MAXN + j0;
                    if (j0 + 1 < n) {
                        *(float2*)&g_G[base] = make_float2(c[mi][ni][h * 2], c[mi][ni][h * 2 + 1]);
                    } else if (j0 < n) {
                        g_G[base] = c[mi][ni][h * 2];
                    }
                }
            }
        }
    }
}

// ---------------- per-row top-K candidates (sim >= thresh, desc, tie -> smaller j) ----------------
__global__ void __launch_bounds__(256) k_scan() {
    if (g_done) return;
    int n = g_n;
    if (n <= 1) return;
    int i = blockIdx.x;
    if (i >= n) return;
    int tid = threadIdx.x;
    float inv_i = g_invnorm[i];

    float          lv[KTOP];
    unsigned short lj[KTOP];
#pragma unroll
    for (int c = 0; c < KTOP; c++) { lv[c] = -1e30f; lj[c] = 0xffff; }
    int cnt = 0;

    for (int j = i + 1 + tid; j < n; j += 256) {
        float v = g_G[(size_t)i * MAXN + j] * inv_i * g_invnorm[j];
        if (v >= THRESH_F) {
            cnt++;
            if (v > lv[KTOP - 1]) {
                float cv = v; unsigned short cj = (unsigned short)j;
#pragma unroll
                for (int c = 0; c < KTOP; c++) {   // strict > keeps earlier (smaller) j on ties
                    if (cv > lv[c]) {
                        float tv = lv[c]; unsigned short tj = lj[c];
                        lv[c] = cv; lj[c] = cj; cv = tv; cj = tj;
                    }
                }
            }
        }
    }

    __shared__ float          sv[256 * KTOP];
    __shared__ unsigned short sj2[256 * KTOP];
    __shared__ int scount;
    if (tid == 0) scount = 0;
    __syncthreads();
#pragma unroll
    for (int c = 0; c < KTOP; c++) { sv[tid * KTOP + c] = lv[c]; sj2[tid * KTOP + c] = lj[c]; }
    if (cnt) atomicAdd(&scount, cnt);
    __syncthreads();

    if (tid == 0) g_trunc[i] = (scount > KTOP) ? 1 : 0;

    if (tid < 32) {
        const unsigned FULL = 0xffffffffu;
        for (int pass = 0; pass < KTOP; pass++) {
            float bv = -1e30f; int bj = 0x10000; int bs = -1;
            for (int t = tid; t < 256 * KTOP; t += 32) {
                float v = sv[t]; int jv = sj2[t];
                if (v > bv || (v == bv && jv < bj)) { bv = v; bj = jv; bs = t; }
            }
            for (int off = 16; off > 0; off >>= 1) {
                float ov = __shfl_down_sync(FULL, bv, off);
                int   oj = __shfl_down_sync(FULL, bj, off);
                int   os = __shfl_down_sync(FULL, bs, off);
                if (ov > bv || (ov == bv && oj < bj)) { bv = ov; bj = oj; bs = os; }
            }
            bv = __shfl_sync(FULL, bv, 0);
            bj = __shfl_sync(FULL, bj, 0);
            bs = __shfl_sync(FULL, bs, 0);
            if (tid == 0) {
                g_topk[i * KTOP + pass] =
                    (bv >= THRESH_F) ? (unsigned short)bj : (unsigned short)0xffff;
                if (bs >= 0) sv[bs] = -1e30f;
            }
            __syncwarp();
        }
    }
}

// ---------------- sequential greedy resolution: 1 block, warp-serial with SMEM state ----------------
__global__ void __launch_bounds__(256) k_greedy() {
    if (g_done) return;
    int n = g_n;
    if (n <= 1) return;
    int tid = threadIdx.x;

    extern __shared__ unsigned char sraw[];
    unsigned short* slist     = (unsigned short*)sraw;                  // MAXN*KTOP ushorts
    unsigned char*  smerged   = sraw + (size_t)MAXN * KTOP * 2;         // MAXN
    unsigned char*  sconsumed = smerged + MAXN;                         // MAXN

    {   // stage candidate lists + clear flags
        const unsigned* src = (const unsigned*)g_topk;
        unsigned* dst = (unsigned*)slist;
        int nv = n * (KTOP / 2);
        for (int x = tid; x < nv; x += 256) dst[x] = src[x];
        for (int x = tid; x < n; x += 256) { smerged[x] = 0; sconsumed[x] = 0; }
    }
    __syncthreads();
    if (tid >= 32) return;

    volatile unsigned char* vm = (volatile unsigned char*)smerged;
    volatile unsigned char* vc = (volatile unsigned char*)sconsumed;
    const unsigned FULL = 0xffffffffu;
    int lane = tid;
    int nm = 0;

    for (int i = 0; i < n; i++) {
        int mi = vm[i];
        if (!mi) {
            int e  = (lane < KTOP) ? (int)slist[i * KTOP + lane] : 0xffff;
            int ok = (e != 0xffff) && (vm[e] == 0);
            unsigned bal = __ballot_sync(FULL, ok);
            if (bal) {
                int first = __ffs(bal) - 1;
                if (lane == first) {
                    vm[e] = 1; vc[e] = 1;
                    g_partner[i] = e;
                    nm++;
                }
            } else {
                int tr = g_trunc[i];
                if (tr) {
                    // rare fallback: full rescan of row i over unmerged j>i
                    float inv_i = g_invnorm[i];
                    float bvv = -1e30f; int bj = 0x7fffffff;
                    for (int j = i + 1 + lane; j < n; j += 32) {
                        if (!vm[j]) {
                            float v = g_G[(size_t)i * MAXN + j] * g_invnorm[j];
                            if (v > bvv) { bvv = v; bj = j; }
                        }
                    }
                    for (int off = 16; off > 0; off >>= 1) {
                        float ov = __shfl_down_sync(FULL, bvv, off);
                        int   oj = __shfl_down_sync(FULL, bj, off);
                        if (ov > bvv || (ov == bvv && oj < bj)) { bvv = ov; bj = oj; }
                    }
                    bvv = __shfl_sync(FULL, bvv, 0);
                    bj  = __shfl_sync(FULL, bj, 0);
                    if (lane == 0) {
                        if (bj < n && bvv * inv_i >= THRESH_F) {
                            vm[bj] = 1; vc[bj] = 1;
                            g_partner[i] = bj;
                            nm++;
                        } else {
                            g_partner[i] = -1;
                        }
                    }
                } else {
                    if (lane == 0) g_partner[i] = -1;
                }
            }
        } else {
            if (lane == 0) g_partner[i] = -1;
        }
        __syncwarp();
    }

    // survivor compaction (order-preserving) + totals
    int base = 0;
    for (int i0 = 0; i0 < n; i0 += 32) {
        int x = i0 + lane;
        int alive = (x < n) && (vc[x] == 0);
        unsigned bal = __ballot_sync(FULL, alive);
        if (alive) g_surv[base + __popc(bal & ((1u << lane) - 1))] = x;
        base += __popc(bal);
    }
    for (int off = 16; off > 0; off >>= 1) nm += __shfl_down_sync(FULL, nm, off);
    if (lane == 0) { g_newn = base; g_nmerge = nm; }
}

// ---------------- fuse + compact into other buffer (fp32 + bf16), recompute norms ----------------
__global__ void __launch_bounds__(128) k_fuse() {
    if (g_done) return;
    if (g_n <= 1) return;
    if (g_nmerge == 0) return;
    int s = blockIdx.x;
    if (s >= g_newn) return;
    int i = g_surv[s];
    int p = g_partner[i];
    int t = threadIdx.x;
    int src = g_src;
    const float4* S  = (const float4*)g_emb[src];
    float4*       Dt = (float4*)g_emb[src ^ 1];

    float4 a = S[(size_t)i * DV + t];
    if (p >= 0) {
        float4 b = S[(size_t)p * DV + t];
        a.x = fminf(a.x + b.x, 1.0f);
        a.y = fminf(a.y + b.y, 1.0f);
        a.z = fminf(a.z + b.z, 1.0f);
        a.w = fminf(a.w + b.w, 1.0f);
    }
    Dt[(size_t)s * DV + t] = a;
    __nv_bfloat162* H = (__nv_bfloat162*)g_embh[src ^ 1];
    H[(size_t)s * 256 + t * 2]     = __floats2bfloat162_rn(a.x, a.y);
    H[(size_t)s * 256 + t * 2 + 1] = __floats2bfloat162_rn(a.z, a.w);

    __shared__ float sred[128];
    sred[t] = a.x * a.x + a.y * a.y + a.z * a.z + a.w * a.w;
    __syncthreads();
    for (int off = 64; off > 0; off >>= 1) {
        if (t < off) sred[t] += sred[t + off];
        __syncthreads();
    }
    if (t == 0) g_invnorm[s] = 1.0f / fmaxf(sqrtf(sred[0]), 1e-8f);
}

// ---------------- advance round state ----------------
__global__ void k_next() {
    if (g_done) return;
    if (g_n <= 1)      { g_done = 1; return; }
    if (g_nmerge == 0) { g_done = 1; return; }
    g_n = g_newn;
    g_src ^= 1;
    if (g_newn <= 1) g_done = 1;
}

// ---------------- emit final embeddings ----------------
__global__ void __launch_bounds__(128) k_copy(float* __restrict__ out, int out_size) {
    int r = blockIdx.x;
    if (r >= g_n) return;
    int t = threadIdx.x;
    size_t idx = (size_t)r * D + (size_t)t * 4;
    const float* src = g_emb[g_src];
    if (idx + 4 <= (size_t)out_size) {
        *(float4*)(out + idx) = *(const float4*)(src + idx);
    } else {
        for (int k = 0; k < 4; k++)
            if (idx + k < (size_t)out_size) out[idx + k] = src[idx + k];
    }
}

extern "C" void kernel_launch(void* const* d_in, const int* in_sizes, int n_in,
                              void* d_out, int out_size) {
    const float* in = (const float*)d_in[0];
    float* out = (float*)d_out;
    int n0 = in_sizes[0] / D;

    cudaFuncSetAttribute(k_greedy, cudaFuncAttributeMaxDynamicSharedMemorySize, GREEDY_SMEM);

    k_init<<<n0, 128>>>(in, n0);
    dim3 gg(MAXN / 128, MAXN / 128);
    for (int r = 0; r < NROUNDS; r++) {
        k_gemm<<<gg, 256>>>();
        k_scan<<<MAXN, 256>>>();
        k_greedy<<<1, 256, GREEDY_SMEM>>>();
        k_fuse<<<MAXN, 128>>>();
        k_next<<<1, 1>>>();
    }
    k_copy<<<MAXN, 128>>>(out, out_size);
}